// round 12
// baseline (speedup 1.0000x reference)
#include <cuda_runtime.h>
#include <cuda_bf16.h>
#include <cstdint>

#define NN 100000
#define NE 400000
#define INF 128
#define HIDF 1024
#define OUTF 64
#define SCAN_B 1024
#define NBLK ((NN + SCAN_B - 1) / SCAN_B)

// ---------------- scratch (device globals; no allocation allowed) ----------------
__device__ float g_deg[NN];
__device__ float g_dinv[NN];
__device__ int g_cnt[NN];
__device__ int g_inc[NN];
__device__ int g_bsum[NBLK];
__device__ int g_offs[NN];
__device__ int g_fill[NN];
__device__ int g_csr_src[NE];
__device__ float g_csr_nrm[NE];
__device__ __align__(256) float g_z[(size_t)NN * OUTF];
__device__ __align__(256) float g_w1t[(size_t)HIDF * INF];   // [hid][in] tf32
__device__ __align__(256) float g_w2t[(size_t)OUTF * HIDF];  // [out][hid] tf32

// ---------------- helpers ----------------
__device__ __forceinline__ uint32_t f2tf32(float x) {
    uint32_t r;
    asm("cvt.rna.tf32.f32 %0, %1;" : "=r"(r) : "f"(x));
    return r;
}
__device__ __forceinline__ void mma16n8k8(float* c, const uint32_t* a, const uint32_t* b) {
    asm volatile(
        "mma.sync.aligned.m16n8k8.row.col.f32.tf32.tf32.f32 "
        "{%0,%1,%2,%3}, {%4,%5,%6,%7}, {%8,%9}, {%0,%1,%2,%3};"
        : "+f"(c[0]), "+f"(c[1]), "+f"(c[2]), "+f"(c[3])
        : "r"(a[0]), "r"(a[1]), "r"(a[2]), "r"(a[3]), "r"(b[0]), "r"(b[1]));
}
__device__ __forceinline__ void ldsm_x4(uint32_t* r, uint32_t addr) {
    asm volatile("ldmatrix.sync.aligned.m8n8.x4.shared.b16 {%0,%1,%2,%3}, [%4];"
                 : "=r"(r[0]), "=r"(r[1]), "=r"(r[2]), "=r"(r[3]) : "r"(addr));
}
__device__ __forceinline__ uint32_t smem_u32(const void* p) {
    uint32_t a;
    asm("{ .reg .u64 t; cvta.to.shared.u64 t, %1; cvt.u32.u64 %0, t; }" : "=r"(a) : "l"(p));
    return a;
}
#define CP_ASYNC16(dst, src) \
    asm volatile("cp.async.cg.shared.global [%0], [%1], 16;" :: "r"(dst), "l"(src))
#define CP_COMMIT() asm volatile("cp.async.commit_group;" ::: "memory")
#define CP_WAIT0() asm volatile("cp.async.wait_group 0;" ::: "memory")

// ---------------- graph prep ----------------
// merged: deg/cnt/fill init + W1^T tf32 + W2^T tf32
#define PREP_MAX (INF * HIDF)   // 131072 >= NN and >= HIDF*OUTF
__global__ void prep_kernel(float* __restrict__ deg, int* __restrict__ cnt,
                            int* __restrict__ fill,
                            const float* __restrict__ W1, float* __restrict__ w1t,
                            const float* __restrict__ W2, float* __restrict__ w2t) {
    int idx = blockIdx.x * blockDim.x + threadIdx.x;
    if (idx < NN) { deg[idx] = 1.0f; cnt[idx] = 0; fill[idx] = 0; }
    if (idx < INF * HIDF) {
        int k = idx / HIDF, n = idx - k * HIDF;
        w1t[(size_t)n * INF + k] = __uint_as_float(f2tf32(W1[idx]));
    }
    if (idx < HIDF * OUTF) {
        int k = idx / OUTF, n = idx - k * OUTF;
        w2t[(size_t)n * HIDF + k] = __uint_as_float(f2tf32(W2[idx]));
    }
}
__global__ void accum_kernel(const int* __restrict__ ei, const float* __restrict__ ew,
                             float* __restrict__ deg, int* __restrict__ cnt, int E) {
    int e = blockIdx.x * blockDim.x + threadIdx.x;
    if (e < E) {
        int d = ei[E + e];
        atomicAdd(&deg[d], ew[e]);
        atomicAdd(&cnt[d], 1);
    }
}
__global__ void dinv_kernel(const float* __restrict__ deg, float* __restrict__ dinv, int n) {
    int i = blockIdx.x * blockDim.x + threadIdx.x;
    if (i < n) {
        float d = deg[i];
        dinv[i] = d > 0.0f ? rsqrtf(d) : 0.0f;
    }
}
__global__ void scan_block_kernel(const int* __restrict__ cnt, int* __restrict__ inc,
                                  int* __restrict__ bsum, int n) {
    __shared__ int s[SCAN_B];
    int i = blockIdx.x * SCAN_B + threadIdx.x;
    int v = (i < n) ? cnt[i] : 0;
    s[threadIdx.x] = v;
    __syncthreads();
    for (int d = 1; d < SCAN_B; d <<= 1) {
        int t = (threadIdx.x >= d) ? s[threadIdx.x - d] : 0;
        __syncthreads();
        s[threadIdx.x] += t;
        __syncthreads();
    }
    if (i < n) inc[i] = s[threadIdx.x];
    if (threadIdx.x == SCAN_B - 1) bsum[blockIdx.x] = s[SCAN_B - 1];
}
__global__ void scan_bsum_kernel(int* __restrict__ bsum, int nb) {
    if (threadIdx.x == 0 && blockIdx.x == 0) {
        int acc = 0;
        for (int b = 0; b < nb; b++) { int t = bsum[b]; bsum[b] = acc; acc += t; }
    }
}
__global__ void scan_final_kernel(const int* __restrict__ cnt, const int* __restrict__ inc,
                                  const int* __restrict__ bsum, int* __restrict__ offs, int n) {
    int i = blockIdx.x * SCAN_B + threadIdx.x;
    if (i < n) offs[i] = bsum[blockIdx.x] + inc[i] - cnt[i];
}
__global__ void fill_csr_kernel(const int* __restrict__ ei, const float* __restrict__ ew,
                                const float* __restrict__ dinv, const int* __restrict__ offs,
                                int* __restrict__ fill, int* __restrict__ csr_src,
                                float* __restrict__ csr_nrm, int E) {
    int e = blockIdx.x * blockDim.x + threadIdx.x;
    if (e >= E) return;
    int s = ei[e], d = ei[E + e];
    int pos = offs[d] + atomicAdd(&fill[d], 1);
    csr_src[pos] = s;
    csr_nrm[pos] = dinv[s] * ew[e] * dinv[d];
}

// one warp per dst node (used for output layer only)
template <int F, bool BIAS>
__global__ void gather_kernel(const int* __restrict__ csr_src, const float* __restrict__ csr_nrm,
                              const int* __restrict__ offs, const int* __restrict__ cnt,
                              const float* __restrict__ dinv, const float* __restrict__ feat,
                              const float* __restrict__ bias, float* __restrict__ out) {
    int warp = (blockIdx.x * blockDim.x + threadIdx.x) >> 5;
    int lane = threadIdx.x & 31;
    if (warp >= NN) return;
    int beg = offs[warp], n = cnt[warp];
    float si = dinv[warp];
    si = si * si;
    float2 v = reinterpret_cast<const float2*>(feat + (size_t)warp * 64)[lane];
    float2 acc;
    acc.x = si * v.x; acc.y = si * v.y;
    for (int j = beg; j < beg + n; j++) {
        int s = csr_src[j];
        float nrm = csr_nrm[j];
        float2 f = reinterpret_cast<const float2*>(feat + (size_t)s * 64)[lane];
        acc.x += nrm * f.x; acc.y += nrm * f.y;
    }
    if (BIAS) {
        float2 b = reinterpret_cast<const float2*>(bias)[lane];
        acc.x += b.x; acc.y += b.y;
    }
    reinterpret_cast<float2*>(out + (size_t)warp * 64)[lane] = acc;
}

// ---------------- fused gather + 2-layer GEMM (R10 core, 256 thr) ----------------
#define AS_STR 132
#define HS_STR 68
#define OFF_AS 0
#define OFF_BS (128 * AS_STR)                       // 2 buffers of [64][132]
#define OFF_HS (OFF_BS + 2 * 64 * AS_STR)
#define OFF_W2 (OFF_HS + 128 * HS_STR)              // 2 buffers of [64][68]
#define FUSED_SMEM ((OFF_W2 + 2 * 64 * HS_STR) * 4)
#define BS_BYTES (64 * AS_STR * 4)
#define W2_BYTES (64 * HS_STR * 4)

__global__ void __launch_bounds__(256) fused_gemm_kernel(
    const float* __restrict__ X,
    const int* __restrict__ csr_src, const float* __restrict__ csr_nrm,
    const int* __restrict__ offs, const int* __restrict__ cnt,
    const float* __restrict__ dinv,
    const float* __restrict__ W1t, const float* __restrict__ b1,
    const float* __restrict__ W2t, float* __restrict__ Z, int M) {
    extern __shared__ uint32_t sm[];
    uint32_t* As = sm + OFF_AS;
    uint32_t* Hs = sm + OFF_HS;

    int tid = threadIdx.x, lane = tid & 31, wid = tid >> 5;
    int wm = wid & 3, wn = wid >> 2;
    int m0 = blockIdx.x * 128;

    uint32_t as_u = smem_u32(sm + OFF_AS);
    uint32_t bs_u = smem_u32(sm + OFF_BS);
    uint32_t hs_u = smem_u32(sm + OFF_HS);
    uint32_t w2_u = smem_u32(sm + OFF_W2);

    int lrow = (((lane >> 3) & 1) << 3) + (lane & 7);
    int lcol = (lane >> 4) << 2;
    int ar = lane >> 2, ac = lane & 3;

    // ---- cp.async chunk loader ----
    auto load_chunk = [&](int ch, int buf) {
        int c0 = ch * 64;
        uint32_t bdst = bs_u + buf * BS_BYTES;
#pragma unroll
        for (int i = 0; i < 8; i++) {
            int u = tid + i * 256;
            int r = u >> 5, c = (u & 31) * 4;
            CP_ASYNC16(bdst + (r * AS_STR + c) * 4,
                       W1t + (size_t)(c0 + r) * INF + c);
        }
        uint32_t wdst = w2_u + buf * W2_BYTES;
#pragma unroll
        for (int i = 0; i < 4; i++) {
            int u = tid + i * 256;
            int r = u >> 4, c = (u & 15) * 4;
            CP_ASYNC16(wdst + (r * HS_STR + c) * 4,
                       W2t + (size_t)r * HIDF + c0 + c);
        }
        CP_COMMIT();
    };

    load_chunk(0, 0);   // prefetch first weight chunk behind the gather

    // ---- stage A tile by GCN gather: row = dinv²·x[row] + Σ nrm·x[src] ----
    // each warp owns 16 rows; each lane owns 4 consecutive cols (float4)
    {
        const float4* x4 = reinterpret_cast<const float4*>(X);
#pragma unroll 1
        for (int i = 0; i < 16; i++) {
            int r = wid * 16 + i;
            int g = m0 + r;
            float4 acc = make_float4(0.f, 0.f, 0.f, 0.f);
            if (g < M) {
                float si = dinv[g];
                float s2 = si * si;
                float4 xv = x4[(size_t)g * 32 + lane];
                acc.x = s2 * xv.x; acc.y = s2 * xv.y; acc.z = s2 * xv.z; acc.w = s2 * xv.w;
                int beg = offs[g], n = cnt[g];
                for (int j = beg; j < beg + n; j++) {
                    int s = csr_src[j];
                    float nrm = csr_nrm[j];
                    float4 f = x4[(size_t)s * 32 + lane];
                    acc.x += nrm * f.x; acc.y += nrm * f.y;
                    acc.z += nrm * f.z; acc.w += nrm * f.w;
                }
            }
            uint32_t* p = As + r * AS_STR + lane * 4;
            p[0] = f2tf32(acc.x); p[1] = f2tf32(acc.y);
            p[2] = f2tf32(acc.z); p[3] = f2tf32(acc.w);
        }
    }

    float acc_out[2][4][4];
#pragma unroll
    for (int mt = 0; mt < 2; mt++)
#pragma unroll
        for (int nt = 0; nt < 4; nt++)
#pragma unroll
            for (int i = 0; i < 4; i++) acc_out[mt][nt][i] = 0.0f;

    for (int ch = 0; ch < HIDF / 64; ch++) {
        int buf = ch & 1;
        CP_WAIT0();
        __syncthreads();
        if (ch + 1 < HIDF / 64) load_chunk(ch + 1, buf ^ 1);

        uint32_t bsb = bs_u + buf * BS_BYTES;
        uint32_t w2b = w2_u + buf * W2_BYTES;

        // ---- mma1: h_chunk[128x64] = A @ W1chunk^T, K=128 ----
        float acc_h[2][4][4];
#pragma unroll
        for (int mt = 0; mt < 2; mt++)
#pragma unroll
            for (int nt = 0; nt < 4; nt++)
#pragma unroll
                for (int i = 0; i < 4; i++) acc_h[mt][nt][i] = 0.0f;
#pragma unroll
        for (int kk = 0; kk < 128; kk += 8) {
            uint32_t a[2][4], bp[2][4];
#pragma unroll
            for (int mt = 0; mt < 2; mt++) {
                int rb = wm * 32 + mt * 16;
                ldsm_x4(a[mt], as_u + ((rb + lrow) * AS_STR + kk + lcol) * 4);
            }
#pragma unroll
            for (int np = 0; np < 2; np++) {
                int nb = wn * 32 + np * 16;
                ldsm_x4(bp[np], bsb + ((nb + lrow) * AS_STR + kk + lcol) * 4);
            }
#pragma unroll
            for (int mt = 0; mt < 2; mt++)
#pragma unroll
                for (int np = 0; np < 2; np++) {
                    uint32_t b0[2] = {bp[np][0], bp[np][2]};
                    uint32_t b1r[2] = {bp[np][1], bp[np][3]};
                    mma16n8k8(acc_h[mt][np * 2 + 0], a[mt], b0);
                    mma16n8k8(acc_h[mt][np * 2 + 1], a[mt], b1r);
                }
        }
        // bias + relu -> Hs (tf32)
        int c0 = ch * 64;
#pragma unroll
        for (int mt = 0; mt < 2; mt++) {
#pragma unroll
            for (int half = 0; half < 2; half++) {
                int row = wm * 32 + mt * 16 + ar + half * 8;
#pragma unroll
                for (int nt = 0; nt < 4; nt++) {
                    int col = wn * 32 + nt * 8 + 2 * ac;
                    float bv0 = __ldg(b1 + c0 + col);
                    float bv1 = __ldg(b1 + c0 + col + 1);
                    float v0 = fmaxf(acc_h[mt][nt][half * 2 + 0] + bv0, 0.0f);
                    float v1 = fmaxf(acc_h[mt][nt][half * 2 + 1] + bv1, 0.0f);
                    uint32_t* p = Hs + row * HS_STR + col;
                    p[0] = f2tf32(v0);
                    p[1] = f2tf32(v1);
                }
            }
        }
        __syncthreads();

        // ---- mma2: acc_out += h_chunk @ W2chunk^T, K=64 ----
#pragma unroll
        for (int kk = 0; kk < 64; kk += 8) {
            uint32_t a[2][4], bp[2][4];
#pragma unroll
            for (int mt = 0; mt < 2; mt++) {
                int rb = wm * 32 + mt * 16;
                ldsm_x4(a[mt], hs_u + ((rb + lrow) * HS_STR + kk + lcol) * 4);
            }
#pragma unroll
            for (int np = 0; np < 2; np++) {
                int nb = wn * 32 + np * 16;
                ldsm_x4(bp[np], w2b + ((nb + lrow) * HS_STR + kk + lcol) * 4);
            }
#pragma unroll
            for (int mt = 0; mt < 2; mt++)
#pragma unroll
                for (int np = 0; np < 2; np++) {
                    uint32_t b0[2] = {bp[np][0], bp[np][2]};
                    uint32_t b1r[2] = {bp[np][1], bp[np][3]};
                    mma16n8k8(acc_out[mt][np * 2 + 0], a[mt], b0);
                    mma16n8k8(acc_out[mt][np * 2 + 1], a[mt], b1r);
                }
        }
    }

    // ---- epilogue: Z tile [128 x 64] ----
#pragma unroll
    for (int mt = 0; mt < 2; mt++) {
#pragma unroll
        for (int half = 0; half < 2; half++) {
            int row = m0 + wm * 32 + mt * 16 + ar + half * 8;
            if (row >= M) continue;
#pragma unroll
            for (int nt = 0; nt < 4; nt++) {
                int col = wn * 32 + nt * 8 + 2 * ac;
                *reinterpret_cast<float2*>(Z + (size_t)row * OUTF + col) =
                    make_float2(acc_out[mt][nt][half * 2 + 0], acc_out[mt][nt][half * 2 + 1]);
            }
        }
    }
}

// ---------------- launch ----------------
extern "C" void kernel_launch(void* const* d_in, const int* in_sizes, int n_in,
                              void* d_out, int out_size) {
    const float* x = (const float*)d_in[0];
    const int* ei = (const int*)d_in[1];
    const float* ew = (const float*)d_in[2];
    const float* W1 = (const float*)d_in[3];
    const float* b1 = (const float*)d_in[4];
    const float* W2 = (const float*)d_in[5];
    const float* b2 = (const float*)d_in[6];
    float* out = (float*)d_out;

    float *deg, *dinv, *z, *w1t, *w2t, *csr_nrm;
    int *cnt, *inc, *bsum, *offs, *fill, *csr_src;
    cudaGetSymbolAddress((void**)&deg, g_deg);
    cudaGetSymbolAddress((void**)&dinv, g_dinv);
    cudaGetSymbolAddress((void**)&z, g_z);
    cudaGetSymbolAddress((void**)&w1t, g_w1t);
    cudaGetSymbolAddress((void**)&w2t, g_w2t);
    cudaGetSymbolAddress((void**)&cnt, g_cnt);
    cudaGetSymbolAddress((void**)&inc, g_inc);
    cudaGetSymbolAddress((void**)&bsum, g_bsum);
    cudaGetSymbolAddress((void**)&offs, g_offs);
    cudaGetSymbolAddress((void**)&fill, g_fill);
    cudaGetSymbolAddress((void**)&csr_src, g_csr_src);
    cudaGetSymbolAddress((void**)&csr_nrm, g_csr_nrm);

    static bool attr_set = false;
    if (!attr_set) {
        cudaFuncSetAttribute(fused_gemm_kernel,
                             cudaFuncAttributeMaxDynamicSharedMemorySize, FUSED_SMEM);
        attr_set = true;
    }

    // 1) merged prep: deg/cnt/fill init + W1^T + W2^T (tf32)
    prep_kernel<<<(PREP_MAX + 255) / 256, 256>>>(deg, cnt, fill, W1, w1t, W2, w2t);
    // 2) degrees + counts
    accum_kernel<<<(NE + 255) / 256, 256>>>(ei, ew, deg, cnt, NE);
    dinv_kernel<<<(NN + 255) / 256, 256>>>(deg, dinv, NN);
    // 3) CSR build
    scan_block_kernel<<<NBLK, SCAN_B>>>(cnt, inc, bsum, NN);
    scan_bsum_kernel<<<1, 32>>>(bsum, NBLK);
    scan_final_kernel<<<NBLK, SCAN_B>>>(cnt, inc, bsum, offs, NN);
    fill_csr_kernel<<<(NE + 255) / 256, 256>>>(ei, ew, dinv, offs, fill, csr_src, csr_nrm, NE);
    // 4) z = relu((Âx)@W1+b1)@W2  (gather fused into A-staging; h stays in SMEM)
    fused_gemm_kernel<<<(NN + 127) / 128, 256, FUSED_SMEM>>>(
        x, csr_src, csr_nrm, offs, cnt, dinv, w1t, b1, w2t, z, NN);
    // 5) out = Â z + b2
    gather_kernel<64, true><<<(NN * 32 + 255) / 256, 256>>>(csr_src, csr_nrm, offs, cnt,
                                                            dinv, z, b2, out);
}

// round 13
// speedup vs baseline: 1.1472x; 1.1472x over previous
#include <cuda_runtime.h>
#include <cuda_bf16.h>
#include <cstdint>

#define NN 100000
#define NE 400000
#define INF 128
#define HIDF 1024
#define OUTF 64
#define SCAN_B 1024
#define NBLK ((NN + SCAN_B - 1) / SCAN_B)

// ---------------- scratch (device globals; no allocation allowed) ----------------
__device__ float g_deg[NN];
__device__ float g_dinv[NN];
__device__ int g_cnt[NN];
__device__ int g_inc[NN];
__device__ int g_bsum[NBLK];
__device__ int g_offs[NN];
__device__ int g_fill[NN];
__device__ int g_csr_src[NE];
__device__ float g_csr_nrm[NE];
__device__ __align__(256) float g_y[(size_t)NN * INF];
__device__ __align__(256) float g_z[(size_t)NN * OUTF];
__device__ __align__(256) float g_w1t[(size_t)HIDF * INF];   // [hid][in] tf32
__device__ __align__(256) float g_w2t[(size_t)OUTF * HIDF];  // [out][hid] tf32

// ---------------- helpers ----------------
__device__ __forceinline__ uint32_t f2tf32(float x) {
    uint32_t r;
    asm("cvt.rna.tf32.f32 %0, %1;" : "=r"(r) : "f"(x));
    return r;
}
__device__ __forceinline__ void mma16n8k8(float* c, const uint32_t* a, const uint32_t* b) {
    asm volatile(
        "mma.sync.aligned.m16n8k8.row.col.f32.tf32.tf32.f32 "
        "{%0,%1,%2,%3}, {%4,%5,%6,%7}, {%8,%9}, {%0,%1,%2,%3};"
        : "+f"(c[0]), "+f"(c[1]), "+f"(c[2]), "+f"(c[3])
        : "r"(a[0]), "r"(a[1]), "r"(a[2]), "r"(a[3]), "r"(b[0]), "r"(b[1]));
}
__device__ __forceinline__ void ldsm_x4(uint32_t* r, uint32_t addr) {
    asm volatile("ldmatrix.sync.aligned.m8n8.x4.shared.b16 {%0,%1,%2,%3}, [%4];"
                 : "=r"(r[0]), "=r"(r[1]), "=r"(r[2]), "=r"(r[3]) : "r"(addr));
}
__device__ __forceinline__ uint32_t smem_u32(const void* p) {
    uint32_t a;
    asm("{ .reg .u64 t; cvta.to.shared.u64 t, %1; cvt.u32.u64 %0, t; }" : "=r"(a) : "l"(p));
    return a;
}
#define CP_ASYNC16(dst, src) \
    asm volatile("cp.async.cg.shared.global [%0], [%1], 16;" :: "r"(dst), "l"(src))
#define CP_COMMIT() asm volatile("cp.async.commit_group;" ::: "memory")
#define CP_WAIT0() asm volatile("cp.async.wait_group 0;" ::: "memory")

// ---------------- graph prep ----------------
// merged: deg/cnt/fill init + W1^T tf32 + W2^T tf32
#define PREP_MAX (INF * HIDF)   // 131072 >= NN and >= HIDF*OUTF
__global__ void prep_kernel(float* __restrict__ deg, int* __restrict__ cnt,
                            int* __restrict__ fill,
                            const float* __restrict__ W1, float* __restrict__ w1t,
                            const float* __restrict__ W2, float* __restrict__ w2t) {
    int idx = blockIdx.x * blockDim.x + threadIdx.x;
    if (idx < NN) { deg[idx] = 1.0f; cnt[idx] = 0; fill[idx] = 0; }
    if (idx < INF * HIDF) {
        int k = idx / HIDF, n = idx - k * HIDF;
        w1t[(size_t)n * INF + k] = __uint_as_float(f2tf32(W1[idx]));
    }
    if (idx < HIDF * OUTF) {
        int k = idx / OUTF, n = idx - k * OUTF;
        w2t[(size_t)n * HIDF + k] = __uint_as_float(f2tf32(W2[idx]));
    }
}
__global__ void accum_kernel(const int* __restrict__ ei, const float* __restrict__ ew,
                             float* __restrict__ deg, int* __restrict__ cnt, int E) {
    int e = blockIdx.x * blockDim.x + threadIdx.x;
    if (e < E) {
        int d = ei[E + e];
        atomicAdd(&deg[d], ew[e]);
        atomicAdd(&cnt[d], 1);
    }
}
__global__ void dinv_kernel(const float* __restrict__ deg, float* __restrict__ dinv, int n) {
    int i = blockIdx.x * blockDim.x + threadIdx.x;
    if (i < n) {
        float d = deg[i];
        dinv[i] = d > 0.0f ? rsqrtf(d) : 0.0f;
    }
}
__global__ void scan_block_kernel(const int* __restrict__ cnt, int* __restrict__ inc,
                                  int* __restrict__ bsum, int n) {
    __shared__ int s[SCAN_B];
    int i = blockIdx.x * SCAN_B + threadIdx.x;
    int v = (i < n) ? cnt[i] : 0;
    s[threadIdx.x] = v;
    __syncthreads();
    for (int d = 1; d < SCAN_B; d <<= 1) {
        int t = (threadIdx.x >= d) ? s[threadIdx.x - d] : 0;
        __syncthreads();
        s[threadIdx.x] += t;
        __syncthreads();
    }
    if (i < n) inc[i] = s[threadIdx.x];
    if (threadIdx.x == SCAN_B - 1) bsum[blockIdx.x] = s[SCAN_B - 1];
}
__global__ void scan_bsum_kernel(int* __restrict__ bsum, int nb) {
    if (threadIdx.x == 0 && blockIdx.x == 0) {
        int acc = 0;
        for (int b = 0; b < nb; b++) { int t = bsum[b]; bsum[b] = acc; acc += t; }
    }
}
__global__ void scan_final_kernel(const int* __restrict__ cnt, const int* __restrict__ inc,
                                  const int* __restrict__ bsum, int* __restrict__ offs, int n) {
    int i = blockIdx.x * SCAN_B + threadIdx.x;
    if (i < n) offs[i] = bsum[blockIdx.x] + inc[i] - cnt[i];
}
__global__ void fill_csr_kernel(const int* __restrict__ ei, const float* __restrict__ ew,
                                const float* __restrict__ dinv, const int* __restrict__ offs,
                                int* __restrict__ fill, int* __restrict__ csr_src,
                                float* __restrict__ csr_nrm, int E) {
    int e = blockIdx.x * blockDim.x + threadIdx.x;
    if (e >= E) return;
    int s = ei[e], d = ei[E + e];
    int pos = offs[d] + atomicAdd(&fill[d], 1);
    csr_src[pos] = s;
    csr_nrm[pos] = dinv[s] * ew[e] * dinv[d];
}

// one warp per dst node
template <int F, bool BIAS>
__global__ void gather_kernel(const int* __restrict__ csr_src, const float* __restrict__ csr_nrm,
                              const int* __restrict__ offs, const int* __restrict__ cnt,
                              const float* __restrict__ dinv, const float* __restrict__ feat,
                              const float* __restrict__ bias, float* __restrict__ out) {
    int warp = (blockIdx.x * blockDim.x + threadIdx.x) >> 5;
    int lane = threadIdx.x & 31;
    if (warp >= NN) return;
    int beg = offs[warp], n = cnt[warp];
    float si = dinv[warp];
    si = si * si;
    if (F == 128) {
        float4 v = reinterpret_cast<const float4*>(feat + (size_t)warp * 128)[lane];
        float4 acc;
        acc.x = si * v.x; acc.y = si * v.y; acc.z = si * v.z; acc.w = si * v.w;
        for (int j = beg; j < beg + n; j++) {
            int s = csr_src[j];
            float nrm = csr_nrm[j];
            float4 f = reinterpret_cast<const float4*>(feat + (size_t)s * 128)[lane];
            acc.x += nrm * f.x; acc.y += nrm * f.y; acc.z += nrm * f.z; acc.w += nrm * f.w;
        }
        reinterpret_cast<float4*>(out + (size_t)warp * 128)[lane] = acc;
    } else {
        float2 v = reinterpret_cast<const float2*>(feat + (size_t)warp * 64)[lane];
        float2 acc;
        acc.x = si * v.x; acc.y = si * v.y;
        for (int j = beg; j < beg + n; j++) {
            int s = csr_src[j];
            float nrm = csr_nrm[j];
            float2 f = reinterpret_cast<const float2*>(feat + (size_t)s * 64)[lane];
            acc.x += nrm * f.x; acc.y += nrm * f.y;
        }
        if (BIAS) {
            float2 b = reinterpret_cast<const float2*>(bias)[lane];
            acc.x += b.x; acc.y += b.y;
        }
        reinterpret_cast<float2*>(out + (size_t)warp * 64)[lane] = acc;
    }
}

// ---------------- fused 2-layer GEMM (256 thr, pipelined ldsm) ----------------
#define AS_STR 132
#define HS_STR 68
#define OFF_AS 0
#define OFF_BS (128 * AS_STR)                       // 2 buffers of [64][132]
#define OFF_HS (OFF_BS + 2 * 64 * AS_STR)
#define OFF_W2 (OFF_HS + 128 * HS_STR)              // 2 buffers of [64][68]
#define FUSED_SMEM ((OFF_W2 + 2 * 64 * HS_STR) * 4)
#define BS_BYTES (64 * AS_STR * 4)
#define W2_BYTES (64 * HS_STR * 4)

__global__ void __launch_bounds__(256) fused_gemm_kernel(
    const float* __restrict__ Y, const float* __restrict__ W1t,
    const float* __restrict__ b1, const float* __restrict__ W2t,
    float* __restrict__ Z, int M) {
    extern __shared__ uint32_t sm[];
    uint32_t* As = sm + OFF_AS;
    uint32_t* Hs = sm + OFF_HS;

    int tid = threadIdx.x, lane = tid & 31, wid = tid >> 5;
    int wm = wid & 3, wn = wid >> 2;
    int m0 = blockIdx.x * 128;

    uint32_t as_u = smem_u32(sm + OFF_AS);
    uint32_t bs_u = smem_u32(sm + OFF_BS);
    uint32_t hs_u = smem_u32(sm + OFF_HS);
    uint32_t w2_u = smem_u32(sm + OFF_W2);

    int lrow = (((lane >> 3) & 1) << 3) + (lane & 7);
    int lcol = (lane >> 4) << 2;
    int ar = lane >> 2, ac = lane & 3;

    // ---- stage Y tile (tf32) ----
#pragma unroll
    for (int i = 0; i < 16; i++) {
        int u = tid + i * 256;
        int r = u >> 5, c = (u & 31) * 4;
        float4 v;
        if (m0 + r < M)
            v = *reinterpret_cast<const float4*>(Y + (size_t)(m0 + r) * INF + c);
        else
            v = make_float4(0.f, 0.f, 0.f, 0.f);
        uint32_t* p = As + r * AS_STR + c;
        p[0] = f2tf32(v.x); p[1] = f2tf32(v.y); p[2] = f2tf32(v.z); p[3] = f2tf32(v.w);
    }

    // ---- cp.async chunk loader ----
    auto load_chunk = [&](int ch, int buf) {
        int c0 = ch * 64;
        uint32_t bdst = bs_u + buf * BS_BYTES;
#pragma unroll
        for (int i = 0; i < 8; i++) {
            int u = tid + i * 256;
            int r = u >> 5, c = (u & 31) * 4;
            CP_ASYNC16(bdst + (r * AS_STR + c) * 4,
                       W1t + (size_t)(c0 + r) * INF + c);
        }
        uint32_t wdst = w2_u + buf * W2_BYTES;
#pragma unroll
        for (int i = 0; i < 4; i++) {
            int u = tid + i * 256;
            int r = u >> 4, c = (u & 15) * 4;
            CP_ASYNC16(wdst + (r * HS_STR + c) * 4,
                       W2t + (size_t)r * HIDF + c0 + c);
        }
        CP_COMMIT();
    };

    load_chunk(0, 0);

    float acc_out[2][4][4];
#pragma unroll
    for (int mt = 0; mt < 2; mt++)
#pragma unroll
        for (int nt = 0; nt < 4; nt++)
#pragma unroll
            for (int i = 0; i < 4; i++) acc_out[mt][nt][i] = 0.0f;

    for (int ch = 0; ch < HIDF / 64; ch++) {
        int buf = ch & 1;
        CP_WAIT0();
        __syncthreads();
        if (ch + 1 < HIDF / 64) load_chunk(ch + 1, buf ^ 1);

        uint32_t bsb = bs_u + buf * BS_BYTES;
        uint32_t w2b = w2_u + buf * W2_BYTES;

        // ---- mma1: h_chunk[128x64] = y_tile @ W1chunk^T, K=128 (pipelined) ----
        float acc_h[2][4][4];
#pragma unroll
        for (int mt = 0; mt < 2; mt++)
#pragma unroll
            for (int nt = 0; nt < 4; nt++)
#pragma unroll
                for (int i = 0; i < 4; i++) acc_h[mt][nt][i] = 0.0f;
        {
            uint32_t a[2][2][4], bp[2][2][4];  // [regbuf][mt/np][4]
#pragma unroll
            for (int mt = 0; mt < 2; mt++)
                ldsm_x4(a[0][mt], as_u + ((wm * 32 + mt * 16 + lrow) * AS_STR + lcol) * 4);
#pragma unroll
            for (int np = 0; np < 2; np++)
                ldsm_x4(bp[0][np], bsb + ((wn * 32 + np * 16 + lrow) * AS_STR + lcol) * 4);
#pragma unroll
            for (int ki = 0; ki < 16; ki++) {
                int cur = ki & 1, nxt = cur ^ 1;
                if (ki + 1 < 16) {
                    int kk2 = (ki + 1) * 8;
#pragma unroll
                    for (int mt = 0; mt < 2; mt++)
                        ldsm_x4(a[nxt][mt],
                                as_u + ((wm * 32 + mt * 16 + lrow) * AS_STR + kk2 + lcol) * 4);
#pragma unroll
                    for (int np = 0; np < 2; np++)
                        ldsm_x4(bp[nxt][np],
                                bsb + ((wn * 32 + np * 16 + lrow) * AS_STR + kk2 + lcol) * 4);
                }
#pragma unroll
                for (int mt = 0; mt < 2; mt++)
#pragma unroll
                    for (int np = 0; np < 2; np++) {
                        uint32_t b0[2] = {bp[cur][np][0], bp[cur][np][2]};
                        uint32_t b1r[2] = {bp[cur][np][1], bp[cur][np][3]};
                        mma16n8k8(acc_h[mt][np * 2 + 0], a[cur][mt], b0);
                        mma16n8k8(acc_h[mt][np * 2 + 1], a[cur][mt], b1r);
                    }
            }
        }
        // bias + relu -> Hs (tf32)
        int c0 = ch * 64;
#pragma unroll
        for (int mt = 0; mt < 2; mt++) {
#pragma unroll
            for (int half = 0; half < 2; half++) {
                int row = wm * 32 + mt * 16 + ar + half * 8;
#pragma unroll
                for (int nt = 0; nt < 4; nt++) {
                    int col = wn * 32 + nt * 8 + 2 * ac;
                    float bv0 = __ldg(b1 + c0 + col);
                    float bv1 = __ldg(b1 + c0 + col + 1);
                    float v0 = fmaxf(acc_h[mt][nt][half * 2 + 0] + bv0, 0.0f);
                    float v1 = fmaxf(acc_h[mt][nt][half * 2 + 1] + bv1, 0.0f);
                    uint32_t* p = Hs + row * HS_STR + col;
                    p[0] = f2tf32(v0);
                    p[1] = f2tf32(v1);
                }
            }
        }
        __syncthreads();

        // ---- mma2: acc_out += h_chunk @ W2chunk^T, K=64 (pipelined) ----
        {
            uint32_t a[2][2][4], bp[2][2][4];
#pragma unroll
            for (int mt = 0; mt < 2; mt++)
                ldsm_x4(a[0][mt], hs_u + ((wm * 32 + mt * 16 + lrow) * HS_STR + lcol) * 4);
#pragma unroll
            for (int np = 0; np < 2; np++)
                ldsm_x4(bp[0][np], w2b + ((wn * 32 + np * 16 + lrow) * HS_STR + lcol) * 4);
#pragma unroll
            for (int ki = 0; ki < 8; ki++) {
                int cur = ki & 1, nxt = cur ^ 1;
                if (ki + 1 < 8) {
                    int kk2 = (ki + 1) * 8;
#pragma unroll
                    for (int mt = 0; mt < 2; mt++)
                        ldsm_x4(a[nxt][mt],
                                hs_u + ((wm * 32 + mt * 16 + lrow) * HS_STR + kk2 + lcol) * 4);
#pragma unroll
                    for (int np = 0; np < 2; np++)
                        ldsm_x4(bp[nxt][np],
                                w2b + ((wn * 32 + np * 16 + lrow) * HS_STR + kk2 + lcol) * 4);
                }
#pragma unroll
                for (int mt = 0; mt < 2; mt++)
#pragma unroll
                    for (int np = 0; np < 2; np++) {
                        uint32_t b0[2] = {bp[cur][np][0], bp[cur][np][2]};
                        uint32_t b1r[2] = {bp[cur][np][1], bp[cur][np][3]};
                        mma16n8k8(acc_out[mt][np * 2 + 0], a[cur][mt], b0);
                        mma16n8k8(acc_out[mt][np * 2 + 1], a[cur][mt], b1r);
                    }
            }
        }
    }

    // ---- epilogue: Z tile [128 x 64] ----
#pragma unroll
    for (int mt = 0; mt < 2; mt++) {
#pragma unroll
        for (int half = 0; half < 2; half++) {
            int row = m0 + wm * 32 + mt * 16 + ar + half * 8;
            if (row >= M) continue;
#pragma unroll
            for (int nt = 0; nt < 4; nt++) {
                int col = wn * 32 + nt * 8 + 2 * ac;
                *reinterpret_cast<float2*>(Z + (size_t)row * OUTF + col) =
                    make_float2(acc_out[mt][nt][half * 2 + 0], acc_out[mt][nt][half * 2 + 1]);
            }
        }
    }
}

// ---------------- launch ----------------
extern "C" void kernel_launch(void* const* d_in, const int* in_sizes, int n_in,
                              void* d_out, int out_size) {
    const float* x = (const float*)d_in[0];
    const int* ei = (const int*)d_in[1];
    const float* ew = (const float*)d_in[2];
    const float* W1 = (const float*)d_in[3];
    const float* b1 = (const float*)d_in[4];
    const float* W2 = (const float*)d_in[5];
    const float* b2 = (const float*)d_in[6];
    float* out = (float*)d_out;

    float *deg, *dinv, *y, *z, *w1t, *w2t, *csr_nrm;
    int *cnt, *inc, *bsum, *offs, *fill, *csr_src;
    cudaGetSymbolAddress((void**)&deg, g_deg);
    cudaGetSymbolAddress((void**)&dinv, g_dinv);
    cudaGetSymbolAddress((void**)&y, g_y);
    cudaGetSymbolAddress((void**)&z, g_z);
    cudaGetSymbolAddress((void**)&w1t, g_w1t);
    cudaGetSymbolAddress((void**)&w2t, g_w2t);
    cudaGetSymbolAddress((void**)&cnt, g_cnt);
    cudaGetSymbolAddress((void**)&inc, g_inc);
    cudaGetSymbolAddress((void**)&bsum, g_bsum);
    cudaGetSymbolAddress((void**)&offs, g_offs);
    cudaGetSymbolAddress((void**)&fill, g_fill);
    cudaGetSymbolAddress((void**)&csr_src, g_csr_src);
    cudaGetSymbolAddress((void**)&csr_nrm, g_csr_nrm);

    static bool attr_set = false;
    if (!attr_set) {
        cudaFuncSetAttribute(fused_gemm_kernel,
                             cudaFuncAttributeMaxDynamicSharedMemorySize, FUSED_SMEM);
        attr_set = true;
    }

    // 1) merged prep: deg/cnt/fill init + W1^T + W2^T (tf32)
    prep_kernel<<<(PREP_MAX + 255) / 256, 256>>>(deg, cnt, fill, W1, w1t, W2, w2t);
    // 2) degrees + counts
    accum_kernel<<<(NE + 255) / 256, 256>>>(ei, ew, deg, cnt, NE);
    dinv_kernel<<<(NN + 255) / 256, 256>>>(deg, dinv, NN);
    // 3) CSR build
    scan_block_kernel<<<NBLK, SCAN_B>>>(cnt, inc, bsum, NN);
    scan_bsum_kernel<<<1, 32>>>(bsum, NBLK);
    scan_final_kernel<<<NBLK, SCAN_B>>>(cnt, inc, bsum, offs, NN);
    fill_csr_kernel<<<(NE + 255) / 256, 256>>>(ei, ew, dinv, offs, fill, csr_src, csr_nrm, NE);
    // 4) y = Â x  (standalone high-occupancy gather)
    gather_kernel<128, false><<<(NN * 32 + 255) / 256, 256>>>(csr_src, csr_nrm, offs, cnt,
                                                              dinv, x, nullptr, y);
    // 5) z = relu(y@W1+b1)@W2  (fused; h stays in SMEM; pipelined ldsm)
    fused_gemm_kernel<<<(NN + 127) / 128, 256, FUSED_SMEM>>>(y, w1t, b1, w2t, z, NN);
    // 6) out = Â z + b2
    gather_kernel<64, true><<<(NN * 32 + 255) / 256, 256>>>(csr_src, csr_nrm, offs, cnt,
                                                            dinv, z, b2, out);
}

// round 15
// speedup vs baseline: 1.8707x; 1.6307x over previous
#include <cuda_runtime.h>
#include <cuda_fp16.h>
#include <cstdint>

#define NN 100000
#define NE 400000
#define INF 128
#define HIDF 1024
#define OUTF 64
#define SCAN_B 1024
#define NBLK ((NN + SCAN_B - 1) / SCAN_B)

// ---------------- scratch (device globals; no allocation allowed) ----------------
__device__ float g_deg[NN];
__device__ float g_dinv[NN];
__device__ int g_cnt[NN];
__device__ int g_inc[NN];
__device__ int g_bsum[NBLK];
__device__ int g_offs[NN];
__device__ int g_fill[NN];
__device__ int g_csr_src[NE];
__device__ float g_csr_nrm[NE];
__device__ __align__(256) float g_y[(size_t)NN * INF];
__device__ __align__(256) float g_z[(size_t)NN * OUTF];
__device__ __align__(256) __half g_w1t[(size_t)HIDF * INF];   // [hid][in] fp16
__device__ __align__(256) __half g_w2t[(size_t)OUTF * HIDF];  // [out][hid] fp16

// ---------------- helpers ----------------
__device__ __forceinline__ void mma16n8k16f16(float* c, const uint32_t* a, const uint32_t* b) {
    asm volatile(
        "mma.sync.aligned.m16n8k16.row.col.f32.f16.f16.f32 "
        "{%0,%1,%2,%3}, {%4,%5,%6,%7}, {%8,%9}, {%0,%1,%2,%3};"
        : "+f"(c[0]), "+f"(c[1]), "+f"(c[2]), "+f"(c[3])
        : "r"(a[0]), "r"(a[1]), "r"(a[2]), "r"(a[3]), "r"(b[0]), "r"(b[1]));
}
__device__ __forceinline__ void ldsm_x4(uint32_t* r, uint32_t addr) {
    asm volatile("ldmatrix.sync.aligned.m8n8.x4.shared.b16 {%0,%1,%2,%3}, [%4];"
                 : "=r"(r[0]), "=r"(r[1]), "=r"(r[2]), "=r"(r[3]) : "r"(addr));
}
__device__ __forceinline__ uint32_t smem_u32(const void* p) {
    uint32_t a;
    asm("{ .reg .u64 t; cvta.to.shared.u64 t, %1; cvt.u32.u64 %0, t; }" : "=r"(a) : "l"(p));
    return a;
}
#define CP_ASYNC16(dst, src) \
    asm volatile("cp.async.cg.shared.global [%0], [%1], 16;" :: "r"(dst), "l"(src))
#define CP_COMMIT() asm volatile("cp.async.commit_group;" ::: "memory")
#define CP_WAIT0() asm volatile("cp.async.wait_group 0;" ::: "memory")

// ---------------- graph prep ----------------
#define PREP_MAX (INF * HIDF)
__global__ void prep_kernel(float* __restrict__ deg, int* __restrict__ cnt,
                            int* __restrict__ fill,
                            const float* __restrict__ W1, __half* __restrict__ w1t,
                            const float* __restrict__ W2, __half* __restrict__ w2t) {
    int idx = blockIdx.x * blockDim.x + threadIdx.x;
    if (idx < NN) { deg[idx] = 1.0f; cnt[idx] = 0; fill[idx] = 0; }
    if (idx < INF * HIDF) {
        int k = idx / HIDF, n = idx - k * HIDF;
        w1t[(size_t)n * INF + k] = __float2half_rn(W1[idx]);
    }
    if (idx < HIDF * OUTF) {
        int k = idx / OUTF, n = idx - k * OUTF;
        w2t[(size_t)n * HIDF + k] = __float2half_rn(W2[idx]);
    }
}
__global__ void accum_kernel(const int* __restrict__ ei, const float* __restrict__ ew,
                             float* __restrict__ deg, int* __restrict__ cnt, int E) {
    int e = blockIdx.x * blockDim.x + threadIdx.x;
    if (e < E) {
        int d = ei[E + e];
        atomicAdd(&deg[d], ew[e]);
        atomicAdd(&cnt[d], 1);
    }
}
__global__ void dinv_kernel(const float* __restrict__ deg, float* __restrict__ dinv, int n) {
    int i = blockIdx.x * blockDim.x + threadIdx.x;
    if (i < n) {
        float d = deg[i];
        dinv[i] = d > 0.0f ? rsqrtf(d) : 0.0f;
    }
}
__global__ void scan_block_kernel(const int* __restrict__ cnt, int* __restrict__ inc,
                                  int* __restrict__ bsum, int n) {
    __shared__ int s[SCAN_B];
    int i = blockIdx.x * SCAN_B + threadIdx.x;
    int v = (i < n) ? cnt[i] : 0;
    s[threadIdx.x] = v;
    __syncthreads();
    for (int d = 1; d < SCAN_B; d <<= 1) {
        int t = (threadIdx.x >= d) ? s[threadIdx.x - d] : 0;
        __syncthreads();
        s[threadIdx.x] += t;
        __syncthreads();
    }
    if (i < n) inc[i] = s[threadIdx.x];
    if (threadIdx.x == SCAN_B - 1) bsum[blockIdx.x] = s[SCAN_B - 1];
}
__global__ void scan_bsum_kernel(int* __restrict__ bsum, int nb) {
    if (threadIdx.x == 0 && blockIdx.x == 0) {
        int acc = 0;
        for (int b = 0; b < nb; b++) { int t = bsum[b]; bsum[b] = acc; acc += t; }
    }
}
__global__ void scan_final_kernel(const int* __restrict__ cnt, const int* __restrict__ inc,
                                  const int* __restrict__ bsum, int* __restrict__ offs, int n) {
    int i = blockIdx.x * SCAN_B + threadIdx.x;
    if (i < n) offs[i] = bsum[blockIdx.x] + inc[i] - cnt[i];
}
__global__ void fill_csr_kernel(const int* __restrict__ ei, const float* __restrict__ ew,
                                const float* __restrict__ dinv, const int* __restrict__ offs,
                                int* __restrict__ fill, int* __restrict__ csr_src,
                                float* __restrict__ csr_nrm, int E) {
    int e = blockIdx.x * blockDim.x + threadIdx.x;
    if (e >= E) return;
    int s = ei[e], d = ei[E + e];
    int pos = offs[d] + atomicAdd(&fill[d], 1);
    csr_src[pos] = s;
    csr_nrm[pos] = dinv[s] * ew[e] * dinv[d];
}

// one warp per dst node
template <int F, bool BIAS>
__global__ void gather_kernel(const int* __restrict__ csr_src, const float* __restrict__ csr_nrm,
                              const int* __restrict__ offs, const int* __restrict__ cnt,
                              const float* __restrict__ dinv, const float* __restrict__ feat,
                              const float* __restrict__ bias, float* __restrict__ out) {
    int warp = (blockIdx.x * blockDim.x + threadIdx.x) >> 5;
    int lane = threadIdx.x & 31;
    if (warp >= NN) return;
    int beg = offs[warp], n = cnt[warp];
    float si = dinv[warp];
    si = si * si;
    if (F == 128) {
        float4 v = reinterpret_cast<const float4*>(feat + (size_t)warp * 128)[lane];
        float4 acc;
        acc.x = si * v.x; acc.y = si * v.y; acc.z = si * v.z; acc.w = si * v.w;
        for (int j = beg; j < beg + n; j++) {
            int s = csr_src[j];
            float nrm = csr_nrm[j];
            float4 f = reinterpret_cast<const float4*>(feat + (size_t)s * 128)[lane];
            acc.x += nrm * f.x; acc.y += nrm * f.y; acc.z += nrm * f.z; acc.w += nrm * f.w;
        }
        reinterpret_cast<float4*>(out + (size_t)warp * 128)[lane] = acc;
    } else {
        float2 v = reinterpret_cast<const float2*>(feat + (size_t)warp * 64)[lane];
        float2 acc;
        acc.x = si * v.x; acc.y = si * v.y;
        for (int j = beg; j < beg + n; j++) {
            int s = csr_src[j];
            float nrm = csr_nrm[j];
            float2 f = reinterpret_cast<const float2*>(feat + (size_t)s * 64)[lane];
            acc.x += nrm * f.x; acc.y += nrm * f.y;
        }
        if (BIAS) {
            float2 b = reinterpret_cast<const float2*>(bias)[lane];
            acc.x += b.x; acc.y += b.y;
        }
        reinterpret_cast<float2*>(out + (size_t)warp * 64)[lane] = acc;
    }
}

// ---------------- fused 2-layer GEMM, fp16 m16n8k16 (256 thr) ----------------
// strides in halves; row pitches 272B / 144B -> banks r*4 mod 32, conflict-free
#define AS_STRH 136
#define HS_STRH 72
#define AS_BYTES (128 * AS_STRH * 2)                 // 34816
#define BS_BYTES (64 * AS_STRH * 2)                  // 17408 per buffer
#define HS_BYTES (128 * HS_STRH * 2)                 // 18432
#define W2_BYTES (64 * HS_STRH * 2)                  // 9216 per buffer
#define OFF_AS_B 0
#define OFF_BS_B AS_BYTES
#define OFF_HS_B (OFF_BS_B + 2 * BS_BYTES)
#define OFF_W2_B (OFF_HS_B + HS_BYTES)
#define FUSED_SMEM (OFF_W2_B + 2 * W2_BYTES)         // 106496 B

__global__ void __launch_bounds__(256) fused_gemm_kernel(
    const float* __restrict__ Y, const __half* __restrict__ W1t,
    const float* __restrict__ b1, const __half* __restrict__ W2t,
    float* __restrict__ Z, int M) {
    extern __shared__ char smc[];
    __half* As = reinterpret_cast<__half*>(smc + OFF_AS_B);
    __half* Hs = reinterpret_cast<__half*>(smc + OFF_HS_B);

    int tid = threadIdx.x, lane = tid & 31, wid = tid >> 5;
    int wm = wid & 3, wn = wid >> 2;
    int m0 = blockIdx.x * 128;

    uint32_t as_u = smem_u32(smc + OFF_AS_B);
    uint32_t bs_u = smem_u32(smc + OFF_BS_B);
    uint32_t hs_u = smem_u32(smc + OFF_HS_B);
    uint32_t w2_u = smem_u32(smc + OFF_W2_B);

    // fp16 ldmatrix canonical addressing: row = lane%16, col half-offset = (lane/16)*8
    int lr16 = lane & 15;
    int lc16 = (lane >> 4) << 3;
    int ar = lane >> 2, ac = lane & 3;  // mma C-fragment coords

    // ---- stage Y tile -> fp16 ----
#pragma unroll
    for (int i = 0; i < 16; i++) {
        int u = tid + i * 256;
        int r = u >> 5, c = (u & 31) * 4;
        float4 v;
        if (m0 + r < M)
            v = *reinterpret_cast<const float4*>(Y + (size_t)(m0 + r) * INF + c);
        else
            v = make_float4(0.f, 0.f, 0.f, 0.f);
        __half2* p = reinterpret_cast<__half2*>(As + r * AS_STRH + c);
        p[0] = __floats2half2_rn(v.x, v.y);
        p[1] = __floats2half2_rn(v.z, v.w);
    }

    // ---- cp.async chunk loader: W1 chunk 64x128 fp16, W2 chunk 64x64 fp16 ----
    auto load_chunk = [&](int ch, int buf) {
        int c0 = ch * 64;
        uint32_t bdst = bs_u + buf * BS_BYTES;
#pragma unroll
        for (int i = 0; i < 4; i++) {
            int u = tid + i * 256;          // 0..1023 16B units (8 halves)
            int r = u >> 4, c = (u & 15) * 8;
            CP_ASYNC16(bdst + (r * AS_STRH + c) * 2,
                       W1t + (size_t)(c0 + r) * INF + c);
        }
        uint32_t wdst = w2_u + buf * W2_BYTES;
#pragma unroll
        for (int i = 0; i < 2; i++) {
            int u = tid + i * 256;          // 0..511 16B units
            int r = u >> 3, c = (u & 7) * 8;
            CP_ASYNC16(wdst + (r * HS_STRH + c) * 2,
                       W2t + (size_t)r * HIDF + c0 + c);
        }
        CP_COMMIT();
    };

    load_chunk(0, 0);

    float acc_out[2][4][4];
#pragma unroll
    for (int mt = 0; mt < 2; mt++)
#pragma unroll
        for (int nt = 0; nt < 4; nt++)
#pragma unroll
            for (int i = 0; i < 4; i++) acc_out[mt][nt][i] = 0.0f;

    for (int ch = 0; ch < HIDF / 64; ch++) {
        int buf = ch & 1;
        CP_WAIT0();
        __syncthreads();
        if (ch + 1 < HIDF / 64) load_chunk(ch + 1, buf ^ 1);

        uint32_t bsb = bs_u + buf * BS_BYTES;
        uint32_t w2b = w2_u + buf * W2_BYTES;

        // ---- mma1: h_chunk[128x64] = y @ W1chunk^T, K=128 (8 k16 iters) ----
        float acc_h[2][4][4];
#pragma unroll
        for (int mt = 0; mt < 2; mt++)
#pragma unroll
            for (int nt = 0; nt < 4; nt++)
#pragma unroll
                for (int i = 0; i < 4; i++) acc_h[mt][nt][i] = 0.0f;
#pragma unroll
        for (int ki = 0; ki < 8; ki++) {
            int kk = ki * 16;
            uint32_t a[2][4], bp[2][4];
#pragma unroll
            for (int mt = 0; mt < 2; mt++) {
                int rb = wm * 32 + mt * 16;
                ldsm_x4(a[mt], as_u + ((rb + lr16) * AS_STRH + kk + lc16) * 2);
            }
#pragma unroll
            for (int np = 0; np < 2; np++) {
                int nb = wn * 32 + np * 16;
                ldsm_x4(bp[np], bsb + ((nb + lr16) * AS_STRH + kk + lc16) * 2);
            }
#pragma unroll
            for (int mt = 0; mt < 2; mt++)
#pragma unroll
                for (int np = 0; np < 2; np++) {
                    uint32_t b0[2] = {bp[np][0], bp[np][2]};
                    uint32_t b1r[2] = {bp[np][1], bp[np][3]};
                    mma16n8k16f16(acc_h[mt][np * 2 + 0], a[mt], b0);
                    mma16n8k16f16(acc_h[mt][np * 2 + 1], a[mt], b1r);
                }
        }
        // bias + relu -> Hs (fp16)
        int c0 = ch * 64;
#pragma unroll
        for (int mt = 0; mt < 2; mt++) {
#pragma unroll
            for (int half = 0; half < 2; half++) {
                int row = wm * 32 + mt * 16 + ar + half * 8;
#pragma unroll
                for (int nt = 0; nt < 4; nt++) {
                    int col = wn * 32 + nt * 8 + 2 * ac;
                    float bv0 = __ldg(b1 + c0 + col);
                    float bv1 = __ldg(b1 + c0 + col + 1);
                    float v0 = fmaxf(acc_h[mt][nt][half * 2 + 0] + bv0, 0.0f);
                    float v1 = fmaxf(acc_h[mt][nt][half * 2 + 1] + bv1, 0.0f);
                    *reinterpret_cast<__half2*>(Hs + row * HS_STRH + col) =
                        __floats2half2_rn(v0, v1);
                }
            }
        }
        __syncthreads();

        // ---- mma2: acc_out += h_chunk @ W2chunk^T, K=64 (4 k16 iters) ----
#pragma unroll
        for (int ki = 0; ki < 4; ki++) {
            int kk = ki * 16;
            uint32_t a[2][4], bp[2][4];
#pragma unroll
            for (int mt = 0; mt < 2; mt++) {
                int rb = wm * 32 + mt * 16;
                ldsm_x4(a[mt], hs_u + ((rb + lr16) * HS_STRH + kk + lc16) * 2);
            }
#pragma unroll
            for (int np = 0; np < 2; np++) {
                int nb = wn * 32 + np * 16;
                ldsm_x4(bp[np], w2b + ((nb + lr16) * HS_STRH + kk + lc16) * 2);
            }
#pragma unroll
            for (int mt = 0; mt < 2; mt++)
#pragma unroll
                for (int np = 0; np < 2; np++) {
                    uint32_t b0[2] = {bp[np][0], bp[np][2]};
                    uint32_t b1r[2] = {bp[np][1], bp[np][3]};
                    mma16n8k16f16(acc_out[mt][np * 2 + 0], a[mt], b0);
                    mma16n8k16f16(acc_out[mt][np * 2 + 1], a[mt], b1r);
                }
        }
    }

    // ---- epilogue: Z tile [128 x 64] ----
#pragma unroll
    for (int mt = 0; mt < 2; mt++) {
#pragma unroll
        for (int half = 0; half < 2; half++) {
            int row = m0 + wm * 32 + mt * 16 + ar + half * 8;
            if (row >= M) continue;
#pragma unroll
            for (int nt = 0; nt < 4; nt++) {
                int col = wn * 32 + nt * 8 + 2 * ac;
                *reinterpret_cast<float2*>(Z + (size_t)row * OUTF + col) =
                    make_float2(acc_out[mt][nt][half * 2 + 0], acc_out[mt][nt][half * 2 + 1]);
            }
        }
    }
}

// ---------------- launch ----------------
extern "C" void kernel_launch(void* const* d_in, const int* in_sizes, int n_in,
                              void* d_out, int out_size) {
    const float* x = (const float*)d_in[0];
    const int* ei = (const int*)d_in[1];
    const float* ew = (const float*)d_in[2];
    const float* W1 = (const float*)d_in[3];
    const float* b1 = (const float*)d_in[4];
    const float* W2 = (const float*)d_in[5];
    const float* b2 = (const float*)d_in[6];
    float* out = (float*)d_out;

    float *deg, *dinv, *y, *z, *csr_nrm;
    __half *w1t, *w2t;
    int *cnt, *inc, *bsum, *offs, *fill, *csr_src;
    cudaGetSymbolAddress((void**)&deg, g_deg);
    cudaGetSymbolAddress((void**)&dinv, g_dinv);
    cudaGetSymbolAddress((void**)&y, g_y);
    cudaGetSymbolAddress((void**)&z, g_z);
    cudaGetSymbolAddress((void**)&w1t, g_w1t);
    cudaGetSymbolAddress((void**)&w2t, g_w2t);
    cudaGetSymbolAddress((void**)&cnt, g_cnt);
    cudaGetSymbolAddress((void**)&inc, g_inc);
    cudaGetSymbolAddress((void**)&bsum, g_bsum);
    cudaGetSymbolAddress((void**)&offs, g_offs);
    cudaGetSymbolAddress((void**)&fill, g_fill);
    cudaGetSymbolAddress((void**)&csr_src, g_csr_src);
    cudaGetSymbolAddress((void**)&csr_nrm, g_csr_nrm);

    static bool attr_set = false;
    if (!attr_set) {
        cudaFuncSetAttribute(fused_gemm_kernel,
                             cudaFuncAttributeMaxDynamicSharedMemorySize, FUSED_SMEM);
        attr_set = true;
    }

    // 1) merged prep: deg/cnt/fill init + W1^T + W2^T (fp16)
    prep_kernel<<<(PREP_MAX + 255) / 256, 256>>>(deg, cnt, fill, W1, w1t, W2, w2t);
    // 2) degrees + counts
    accum_kernel<<<(NE + 255) / 256, 256>>>(ei, ew, deg, cnt, NE);
    dinv_kernel<<<(NN + 255) / 256, 256>>>(deg, dinv, NN);
    // 3) CSR build
    scan_block_kernel<<<NBLK, SCAN_B>>>(cnt, inc, bsum, NN);
    scan_bsum_kernel<<<1, 32>>>(bsum, NBLK);
    scan_final_kernel<<<NBLK, SCAN_B>>>(cnt, inc, bsum, offs, NN);
    fill_csr_kernel<<<(NE + 255) / 256, 256>>>(ei, ew, dinv, offs, fill, csr_src, csr_nrm, NE);
    // 4) y = Â x
    gather_kernel<128, false><<<(NN * 32 + 255) / 256, 256>>>(csr_src, csr_nrm, offs, cnt,
                                                              dinv, x, nullptr, y);
    // 5) z = relu(y@W1+b1)@W2  (fused fp16 tensor cores; h stays in SMEM)
    fused_gemm_kernel<<<(NN + 127) / 128, 256, FUSED_SMEM>>>(y, w1t, b1, w2t, z, NN);
    // 6) out = Â z + b2
    gather_kernel<64, true><<<(NN * 32 + 255) / 256, 256>>>(csr_src, csr_nrm, offs, cnt,
                                                            dinv, z, b2, out);
}

// round 16
// speedup vs baseline: 1.9915x; 1.0646x over previous
#include <cuda_runtime.h>
#include <cuda_fp16.h>
#include <cstdint>

#define NN 100000
#define NE 400000
#define INF 128
#define HIDF 1024
#define OUTF 64
#define SCAN_B 1024
#define NBLK ((NN + SCAN_B - 1) / SCAN_B)

// ---------------- scratch (device globals; no allocation allowed) ----------------
__device__ float g_deg[NN];
__device__ float g_dinv[NN];
__device__ int g_cnt[NN];
__device__ int g_inc[NN];
__device__ int g_bsum[NBLK];
__device__ int g_offs[NN];
__device__ int g_fill[NN];
__device__ int g_csr_src[NE];
__device__ float g_csr_nrm[NE];
__device__ __align__(256) __half g_y[(size_t)NN * INF];       // aggregated x (fp16)
__device__ __align__(256) float g_z[(size_t)NN * OUTF];
__device__ __align__(256) __half g_w1t[(size_t)HIDF * INF];   // [hid][in] fp16
__device__ __align__(256) __half g_w2t[(size_t)OUTF * HIDF];  // [out][hid] fp16

// ---------------- helpers ----------------
__device__ __forceinline__ void mma16n8k16f16(float* c, const uint32_t* a, const uint32_t* b) {
    asm volatile(
        "mma.sync.aligned.m16n8k16.row.col.f32.f16.f16.f32 "
        "{%0,%1,%2,%3}, {%4,%5,%6,%7}, {%8,%9}, {%0,%1,%2,%3};"
        : "+f"(c[0]), "+f"(c[1]), "+f"(c[2]), "+f"(c[3])
        : "r"(a[0]), "r"(a[1]), "r"(a[2]), "r"(a[3]), "r"(b[0]), "r"(b[1]));
}
__device__ __forceinline__ void ldsm_x4(uint32_t* r, uint32_t addr) {
    asm volatile("ldmatrix.sync.aligned.m8n8.x4.shared.b16 {%0,%1,%2,%3}, [%4];"
                 : "=r"(r[0]), "=r"(r[1]), "=r"(r[2]), "=r"(r[3]) : "r"(addr));
}
__device__ __forceinline__ uint32_t smem_u32(const void* p) {
    uint32_t a;
    asm("{ .reg .u64 t; cvta.to.shared.u64 t, %1; cvt.u32.u64 %0, t; }" : "=r"(a) : "l"(p));
    return a;
}
#define CP_ASYNC16(dst, src) \
    asm volatile("cp.async.cg.shared.global [%0], [%1], 16;" :: "r"(dst), "l"(src))
#define CP_COMMIT() asm volatile("cp.async.commit_group;" ::: "memory")
#define CP_WAIT0() asm volatile("cp.async.wait_group 0;" ::: "memory")

// ---------------- graph prep ----------------
#define PREP_MAX (INF * HIDF)
__global__ void prep_kernel(float* __restrict__ deg, int* __restrict__ cnt,
                            int* __restrict__ fill,
                            const float* __restrict__ W1, __half* __restrict__ w1t,
                            const float* __restrict__ W2, __half* __restrict__ w2t) {
    int idx = blockIdx.x * blockDim.x + threadIdx.x;
    if (idx < NN) { deg[idx] = 1.0f; cnt[idx] = 0; fill[idx] = 0; }
    if (idx < INF * HIDF) {
        int k = idx / HIDF, n = idx - k * HIDF;
        w1t[(size_t)n * INF + k] = __float2half_rn(W1[idx]);
    }
    if (idx < HIDF * OUTF) {
        int k = idx / OUTF, n = idx - k * OUTF;
        w2t[(size_t)n * HIDF + k] = __float2half_rn(W2[idx]);
    }
}
__global__ void accum_kernel(const int* __restrict__ ei, const float* __restrict__ ew,
                             float* __restrict__ deg, int* __restrict__ cnt, int E) {
    int e = blockIdx.x * blockDim.x + threadIdx.x;
    if (e < E) {
        int d = ei[E + e];
        atomicAdd(&deg[d], ew[e]);
        atomicAdd(&cnt[d], 1);
    }
}
__global__ void dinv_kernel(const float* __restrict__ deg, float* __restrict__ dinv, int n) {
    int i = blockIdx.x * blockDim.x + threadIdx.x;
    if (i < n) {
        float d = deg[i];
        dinv[i] = d > 0.0f ? rsqrtf(d) : 0.0f;
    }
}
__global__ void scan_block_kernel(const int* __restrict__ cnt, int* __restrict__ inc,
                                  int* __restrict__ bsum, int n) {
    __shared__ int s[SCAN_B];
    int i = blockIdx.x * SCAN_B + threadIdx.x;
    int v = (i < n) ? cnt[i] : 0;
    s[threadIdx.x] = v;
    __syncthreads();
    for (int d = 1; d < SCAN_B; d <<= 1) {
        int t = (threadIdx.x >= d) ? s[threadIdx.x - d] : 0;
        __syncthreads();
        s[threadIdx.x] += t;
        __syncthreads();
    }
    if (i < n) inc[i] = s[threadIdx.x];
    if (threadIdx.x == SCAN_B - 1) bsum[blockIdx.x] = s[SCAN_B - 1];
}
__global__ void scan_bsum_kernel(int* __restrict__ bsum, int nb) {
    if (threadIdx.x == 0 && blockIdx.x == 0) {
        int acc = 0;
        for (int b = 0; b < nb; b++) { int t = bsum[b]; bsum[b] = acc; acc += t; }
    }
}
__global__ void scan_final_kernel(const int* __restrict__ cnt, const int* __restrict__ inc,
                                  const int* __restrict__ bsum, int* __restrict__ offs, int n) {
    int i = blockIdx.x * SCAN_B + threadIdx.x;
    if (i < n) offs[i] = bsum[blockIdx.x] + inc[i] - cnt[i];
}
__global__ void fill_csr_kernel(const int* __restrict__ ei, const float* __restrict__ ew,
                                const float* __restrict__ dinv, const int* __restrict__ offs,
                                int* __restrict__ fill, int* __restrict__ csr_src,
                                float* __restrict__ csr_nrm, int E) {
    int e = blockIdx.x * blockDim.x + threadIdx.x;
    if (e >= E) return;
    int s = ei[e], d = ei[E + e];
    int pos = offs[d] + atomicAdd(&fill[d], 1);
    csr_src[pos] = s;
    csr_nrm[pos] = dinv[s] * ew[e] * dinv[d];
}

// gather for layer 1: fp32 accumulate, fp16 output
__global__ void gather_h_kernel(const int* __restrict__ csr_src, const float* __restrict__ csr_nrm,
                                const int* __restrict__ offs, const int* __restrict__ cnt,
                                const float* __restrict__ dinv, const float* __restrict__ feat,
                                __half* __restrict__ out) {
    int warp = (blockIdx.x * blockDim.x + threadIdx.x) >> 5;
    int lane = threadIdx.x & 31;
    if (warp >= NN) return;
    int beg = offs[warp], n = cnt[warp];
    float si = dinv[warp];
    si = si * si;
    float4 v = reinterpret_cast<const float4*>(feat + (size_t)warp * 128)[lane];
    float4 acc;
    acc.x = si * v.x; acc.y = si * v.y; acc.z = si * v.z; acc.w = si * v.w;
    for (int j = beg; j < beg + n; j++) {
        int s = csr_src[j];
        float nrm = csr_nrm[j];
        float4 f = reinterpret_cast<const float4*>(feat + (size_t)s * 128)[lane];
        acc.x += nrm * f.x; acc.y += nrm * f.y; acc.z += nrm * f.z; acc.w += nrm * f.w;
    }
    __half2 h0 = __floats2half2_rn(acc.x, acc.y);
    __half2 h1 = __floats2half2_rn(acc.z, acc.w);
    reinterpret_cast<__half2*>(out + (size_t)warp * 128)[lane * 2 + 0] = h0;
    reinterpret_cast<__half2*>(out + (size_t)warp * 128)[lane * 2 + 1] = h1;
}

// gather for output layer: fp32, + bias
__global__ void gather_out_kernel(const int* __restrict__ csr_src, const float* __restrict__ csr_nrm,
                                  const int* __restrict__ offs, const int* __restrict__ cnt,
                                  const float* __restrict__ dinv, const float* __restrict__ feat,
                                  const float* __restrict__ bias, float* __restrict__ out) {
    int warp = (blockIdx.x * blockDim.x + threadIdx.x) >> 5;
    int lane = threadIdx.x & 31;
    if (warp >= NN) return;
    int beg = offs[warp], n = cnt[warp];
    float si = dinv[warp];
    si = si * si;
    float2 v = reinterpret_cast<const float2*>(feat + (size_t)warp * 64)[lane];
    float2 acc;
    acc.x = si * v.x; acc.y = si * v.y;
    for (int j = beg; j < beg + n; j++) {
        int s = csr_src[j];
        float nrm = csr_nrm[j];
        float2 f = reinterpret_cast<const float2*>(feat + (size_t)s * 64)[lane];
        acc.x += nrm * f.x; acc.y += nrm * f.y;
    }
    float2 b = reinterpret_cast<const float2*>(bias)[lane];
    acc.x += b.x; acc.y += b.y;
    reinterpret_cast<float2*>(out + (size_t)warp * 64)[lane] = acc;
}

// ---------------- fused 2-layer GEMM, fp16 m16n8k16 (256 thr, 2 CTA/SM) ----------------
#define AS_STRH 136
#define HS_STRH 72
#define AS_BYTES (128 * AS_STRH * 2)                 // 34816
#define BS_BYTES (64 * AS_STRH * 2)                  // 17408 per buffer
#define HS_BYTES (128 * HS_STRH * 2)                 // 18432
#define W2_BYTES (64 * HS_STRH * 2)                  // 9216 per buffer
#define OFF_AS_B 0
#define OFF_BS_B AS_BYTES
#define OFF_HS_B (OFF_BS_B + 2 * BS_BYTES)
#define OFF_W2_B (OFF_HS_B + HS_BYTES)
#define FUSED_SMEM (OFF_W2_B + 2 * W2_BYTES)         // 106496 B -> 2 CTAs/SM

__global__ void __launch_bounds__(256, 2) fused_gemm_kernel(
    const __half* __restrict__ Y, const __half* __restrict__ W1t,
    const float* __restrict__ b1, const __half* __restrict__ W2t,
    float* __restrict__ Z, int M) {
    extern __shared__ char smc[];
    __half* Hs = reinterpret_cast<__half*>(smc + OFF_HS_B);

    int tid = threadIdx.x, lane = tid & 31, wid = tid >> 5;
    int wm = wid & 3, wn = wid >> 2;
    int m0 = blockIdx.x * 128;

    uint32_t as_u = smem_u32(smc + OFF_AS_B);
    uint32_t bs_u = smem_u32(smc + OFF_BS_B);
    uint32_t hs_u = smem_u32(smc + OFF_HS_B);
    uint32_t w2_u = smem_u32(smc + OFF_W2_B);

    int lr16 = lane & 15;
    int lc16 = (lane >> 4) << 3;
    int ar = lane >> 2, ac = lane & 3;

    // ---- stage Y tile via cp.async (fp16 in gmem; 2048 16B-units, 8 iters) ----
    // rows beyond M read row M-1 (safe, results discarded at epilogue)
#pragma unroll
    for (int i = 0; i < 8; i++) {
        int u = tid + i * 256;
        int r = u >> 4, c = (u & 15) * 8;
        int gr = m0 + r < M ? m0 + r : M - 1;
        CP_ASYNC16(as_u + (r * AS_STRH + c) * 2, Y + (size_t)gr * INF + c);
    }

    // ---- cp.async chunk loader: W1 chunk 64x128 fp16, W2 chunk 64x64 fp16 ----
    auto load_chunk = [&](int ch, int buf) {
        int c0 = ch * 64;
        uint32_t bdst = bs_u + buf * BS_BYTES;
#pragma unroll
        for (int i = 0; i < 4; i++) {
            int u = tid + i * 256;
            int r = u >> 4, c = (u & 15) * 8;
            CP_ASYNC16(bdst + (r * AS_STRH + c) * 2,
                       W1t + (size_t)(c0 + r) * INF + c);
        }
        uint32_t wdst = w2_u + buf * W2_BYTES;
#pragma unroll
        for (int i = 0; i < 2; i++) {
            int u = tid + i * 256;
            int r = u >> 3, c = (u & 7) * 8;
            CP_ASYNC16(wdst + (r * HS_STRH + c) * 2,
                       W2t + (size_t)r * HIDF + c0 + c);
        }
        CP_COMMIT();
    };

    CP_COMMIT();        // group for A tile
    load_chunk(0, 0);

    float acc_out[2][4][4];
#pragma unroll
    for (int mt = 0; mt < 2; mt++)
#pragma unroll
        for (int nt = 0; nt < 4; nt++)
#pragma unroll
            for (int i = 0; i < 4; i++) acc_out[mt][nt][i] = 0.0f;

    for (int ch = 0; ch < HIDF / 64; ch++) {
        int buf = ch & 1;
        CP_WAIT0();
        __syncthreads();
        if (ch + 1 < HIDF / 64) load_chunk(ch + 1, buf ^ 1);

        uint32_t bsb = bs_u + buf * BS_BYTES;
        uint32_t w2b = w2_u + buf * W2_BYTES;

        // ---- mma1: h_chunk[128x64] = y @ W1chunk^T, K=128 (8 k16 iters) ----
        float acc_h[2][4][4];
#pragma unroll
        for (int mt = 0; mt < 2; mt++)
#pragma unroll
            for (int nt = 0; nt < 4; nt++)
#pragma unroll
                for (int i = 0; i < 4; i++) acc_h[mt][nt][i] = 0.0f;
#pragma unroll
        for (int ki = 0; ki < 8; ki++) {
            int kk = ki * 16;
            uint32_t a[2][4], bp[2][4];
#pragma unroll
            for (int mt = 0; mt < 2; mt++) {
                int rb = wm * 32 + mt * 16;
                ldsm_x4(a[mt], as_u + ((rb + lr16) * AS_STRH + kk + lc16) * 2);
            }
#pragma unroll
            for (int np = 0; np < 2; np++) {
                int nb = wn * 32 + np * 16;
                ldsm_x4(bp[np], bsb + ((nb + lr16) * AS_STRH + kk + lc16) * 2);
            }
#pragma unroll
            for (int mt = 0; mt < 2; mt++)
#pragma unroll
                for (int np = 0; np < 2; np++) {
                    uint32_t b0[2] = {bp[np][0], bp[np][2]};
                    uint32_t b1r[2] = {bp[np][1], bp[np][3]};
                    mma16n8k16f16(acc_h[mt][np * 2 + 0], a[mt], b0);
                    mma16n8k16f16(acc_h[mt][np * 2 + 1], a[mt], b1r);
                }
        }
        // bias + relu -> Hs (fp16)
        int c0 = ch * 64;
#pragma unroll
        for (int mt = 0; mt < 2; mt++) {
#pragma unroll
            for (int half = 0; half < 2; half++) {
                int row = wm * 32 + mt * 16 + ar + half * 8;
#pragma unroll
                for (int nt = 0; nt < 4; nt++) {
                    int col = wn * 32 + nt * 8 + 2 * ac;
                    float bv0 = __ldg(b1 + c0 + col);
                    float bv1 = __ldg(b1 + c0 + col + 1);
                    float v0 = fmaxf(acc_h[mt][nt][half * 2 + 0] + bv0, 0.0f);
                    float v1 = fmaxf(acc_h[mt][nt][half * 2 + 1] + bv1, 0.0f);
                    *reinterpret_cast<__half2*>(Hs + row * HS_STRH + col) =
                        __floats2half2_rn(v0, v1);
                }
            }
        }
        __syncthreads();

        // ---- mma2: acc_out += h_chunk @ W2chunk^T, K=64 (4 k16 iters) ----
#pragma unroll
        for (int ki = 0; ki < 4; ki++) {
            int kk = ki * 16;
            uint32_t a[2][4], bp[2][4];
#pragma unroll
            for (int mt = 0; mt < 2; mt++) {
                int rb = wm * 32 + mt * 16;
                ldsm_x4(a[mt], hs_u + ((rb + lr16) * HS_STRH + kk + lc16) * 2);
            }
#pragma unroll
            for (int np = 0; np < 2; np++) {
                int nb = wn * 32 + np * 16;
                ldsm_x4(bp[np], w2b + ((nb + lr16) * HS_STRH + kk + lc16) * 2);
            }
#pragma unroll
            for (int mt = 0; mt < 2; mt++)
#pragma unroll
                for (int np = 0; np < 2; np++) {
                    uint32_t b0[2] = {bp[np][0], bp[np][2]};
                    uint32_t b1r[2] = {bp[np][1], bp[np][3]};
                    mma16n8k16f16(acc_out[mt][np * 2 + 0], a[mt], b0);
                    mma16n8k16f16(acc_out[mt][np * 2 + 1], a[mt], b1r);
                }
        }
    }

    // ---- epilogue: Z tile [128 x 64] ----
#pragma unroll
    for (int mt = 0; mt < 2; mt++) {
#pragma unroll
        for (int half = 0; half < 2; half++) {
            int row = m0 + wm * 32 + mt * 16 + ar + half * 8;
            if (row >= M) continue;
#pragma unroll
            for (int nt = 0; nt < 4; nt++) {
                int col = wn * 32 + nt * 8 + 2 * ac;
                *reinterpret_cast<float2*>(Z + (size_t)row * OUTF + col) =
                    make_float2(acc_out[mt][nt][half * 2 + 0], acc_out[mt][nt][half * 2 + 1]);
            }
        }
    }
}

// ---------------- launch ----------------
extern "C" void kernel_launch(void* const* d_in, const int* in_sizes, int n_in,
                              void* d_out, int out_size) {
    const float* x = (const float*)d_in[0];
    const int* ei = (const int*)d_in[1];
    const float* ew = (const float*)d_in[2];
    const float* W1 = (const float*)d_in[3];
    const float* b1 = (const float*)d_in[4];
    const float* W2 = (const float*)d_in[5];
    const float* b2 = (const float*)d_in[6];
    float* out = (float*)d_out;

    float *deg, *dinv, *z, *csr_nrm;
    __half *y, *w1t, *w2t;
    int *cnt, *inc, *bsum, *offs, *fill, *csr_src;
    cudaGetSymbolAddress((void**)&deg, g_deg);
    cudaGetSymbolAddress((void**)&dinv, g_dinv);
    cudaGetSymbolAddress((void**)&y, g_y);
    cudaGetSymbolAddress((void**)&z, g_z);
    cudaGetSymbolAddress((void**)&w1t, g_w1t);
    cudaGetSymbolAddress((void**)&w2t, g_w2t);
    cudaGetSymbolAddress((void**)&cnt, g_cnt);
    cudaGetSymbolAddress((void**)&inc, g_inc);
    cudaGetSymbolAddress((void**)&bsum, g_bsum);
    cudaGetSymbolAddress((void**)&offs, g_offs);
    cudaGetSymbolAddress((void**)&fill, g_fill);
    cudaGetSymbolAddress((void**)&csr_src, g_csr_src);
    cudaGetSymbolAddress((void**)&csr_nrm, g_csr_nrm);

    static bool attr_set = false;
    if (!attr_set) {
        cudaFuncSetAttribute(fused_gemm_kernel,
                             cudaFuncAttributeMaxDynamicSharedMemorySize, FUSED_SMEM);
        attr_set = true;
    }

    // 1) merged prep: deg/cnt/fill init + W1^T + W2^T (fp16)
    prep_kernel<<<(PREP_MAX + 255) / 256, 256>>>(deg, cnt, fill, W1, w1t, W2, w2t);
    // 2) degrees + counts
    accum_kernel<<<(NE + 255) / 256, 256>>>(ei, ew, deg, cnt, NE);
    dinv_kernel<<<(NN + 255) / 256, 256>>>(deg, dinv, NN);
    // 3) CSR build
    scan_block_kernel<<<NBLK, SCAN_B>>>(cnt, inc, bsum, NN);
    scan_bsum_kernel<<<1, 32>>>(bsum, NBLK);
    scan_final_kernel<<<NBLK, SCAN_B>>>(cnt, inc, bsum, offs, NN);
    fill_csr_kernel<<<(NE + 255) / 256, 256>>>(ei, ew, dinv, offs, fill, csr_src, csr_nrm, NE);
    // 4) y = Â x  (fp16 output)
    gather_h_kernel<<<(NN * 32 + 255) / 256, 256>>>(csr_src, csr_nrm, offs, cnt, dinv, x, y);
    // 5) z = relu(y@W1+b1)@W2  (fused fp16 tensor cores; h stays in SMEM; 2 CTA/SM)
    fused_gemm_kernel<<<(NN + 127) / 128, 256, FUSED_SMEM>>>(y, w1t, b1, w2t, z, NN);
    // 6) out = Â z + b2
    gather_out_kernel<<<(NN * 32 + 255) / 256, 256>>>(csr_src, csr_nrm, offs, cnt,
                                                      dinv, z, b2, out);
}